// round 2
// baseline (speedup 1.0000x reference)
#include <cuda_runtime.h>
#include <math.h>

#define N 4096
#define D 2048
#define MARGIN 0.3f

#define TI 64
#define TJ 64
#define TK 16
#define COLSPLIT 8   // blocks in y; each block covers N/COLSPLIT = 512 columns

// Static device scratch (no allocation allowed)
__device__ float g_sq[N];
__device__ int   g_lab[N];
__device__ float g_ap[N];   // hardest positive (max dist), >= 0
__device__ float g_an[N];   // hardest negative (min dist), init +inf

// ---------------------------------------------------------------------------
// Kernel 1: per-row squared norm, label copy, accumulator init
// NOTE: labels are int32 on device (JAX default config downcasts int64).
// ---------------------------------------------------------------------------
__global__ void prep_kernel(const float* __restrict__ F,
                            const int* __restrict__ lab) {
    int row = blockIdx.x;
    const float4* f4 = reinterpret_cast<const float4*>(F + (size_t)row * D);
    float s = 0.f;
    // D/4 = 512 float4 elements; 256 threads -> 2 each
    for (int k = threadIdx.x; k < D / 4; k += blockDim.x) {
        float4 v = f4[k];
        s += v.x * v.x + v.y * v.y + v.z * v.z + v.w * v.w;
    }
    __shared__ float red[8];
    #pragma unroll
    for (int o = 16; o; o >>= 1) s += __shfl_xor_sync(0xffffffffu, s, o);
    if ((threadIdx.x & 31) == 0) red[threadIdx.x >> 5] = s;
    __syncthreads();
    if (threadIdx.x == 0) {
        float t = 0.f;
        #pragma unroll
        for (int w = 0; w < 8; w++) t += red[w];
        g_sq[row]  = t;
        g_lab[row] = lab[row];
        g_ap[row]  = 0.f;
        g_an[row]  = __int_as_float(0x7f800000);  // +inf
    }
}

// ---------------------------------------------------------------------------
// Kernel 2: fused Gram-tile GEMM + distance + batch-hard mining
// Block: 256 threads (16x16), computes a 64-row slab against a 512-col range.
// Each thread owns a 4x4 micro-tile.
// ---------------------------------------------------------------------------
__global__ __launch_bounds__(256, 4)
void dist_mine_kernel(const float* __restrict__ F) {
    __shared__ float As[TK][TI];
    __shared__ float Bs[TK][TJ];

    const int tid = threadIdx.x;
    const int tx = tid & 15;        // column group within tile
    const int ty = tid >> 4;        // row group within tile
    const int rowBase = blockIdx.x * TI;
    const int colsPer = N / COLSPLIT;           // 512
    const int colBeg  = blockIdx.y * colsPer;

    // per-thread row-local state (4 rows: rowBase + ty*4 + a)
    float ap[4], an[4];
    #pragma unroll
    for (int a = 0; a < 4; a++) { ap[a] = 0.f; an[a] = __int_as_float(0x7f800000); }

    // cache row-side sq/labels for our 4 rows
    float sqi[4]; int li[4];
    #pragma unroll
    for (int a = 0; a < 4; a++) {
        sqi[a] = g_sq[rowBase + ty * 4 + a];
        li[a]  = g_lab[rowBase + ty * 4 + a];
    }

    // global->smem load mapping: thread loads one float4 of a 64x16 tile
    const int ldR  = tid >> 2;      // 0..63 row within tile
    const int ldKq = tid & 3;       // 0..3  (float4 index within 16-wide k chunk)

    for (int jt = 0; jt < colsPer; jt += TJ) {
        const int colTile = colBeg + jt;

        float acc[4][4];
        #pragma unroll
        for (int a = 0; a < 4; a++)
            #pragma unroll
            for (int b = 0; b < 4; b++) acc[a][b] = 0.f;

        for (int k0 = 0; k0 < D; k0 += TK) {
            // load A tile (rows) and B tile (cols), transposed into [k][idx]
            float4 va = *reinterpret_cast<const float4*>(
                F + (size_t)(rowBase + ldR) * D + k0 + ldKq * 4);
            float4 vb = *reinterpret_cast<const float4*>(
                F + (size_t)(colTile + ldR) * D + k0 + ldKq * 4);
            __syncthreads();  // protect previous iteration's reads
            As[ldKq * 4 + 0][ldR] = va.x;
            As[ldKq * 4 + 1][ldR] = va.y;
            As[ldKq * 4 + 2][ldR] = va.z;
            As[ldKq * 4 + 3][ldR] = va.w;
            Bs[ldKq * 4 + 0][ldR] = vb.x;
            Bs[ldKq * 4 + 1][ldR] = vb.y;
            Bs[ldKq * 4 + 2][ldR] = vb.z;
            Bs[ldKq * 4 + 3][ldR] = vb.w;
            __syncthreads();

            #pragma unroll
            for (int k = 0; k < TK; k++) {
                float4 a4 = *reinterpret_cast<const float4*>(&As[k][ty * 4]);
                float4 b4 = *reinterpret_cast<const float4*>(&Bs[k][tx * 4]);
                float ar[4] = {a4.x, a4.y, a4.z, a4.w};
                float br[4] = {b4.x, b4.y, b4.z, b4.w};
                #pragma unroll
                for (int a = 0; a < 4; a++)
                    #pragma unroll
                    for (int b = 0; b < 4; b++)
                        acc[a][b] = fmaf(ar[a], br[b], acc[a][b]);
            }
        }

        // epilogue for this 64x64 tile: distances + masked max/min
        #pragma unroll
        for (int b = 0; b < 4; b++) {
            const int j = colTile + tx * 4 + b;
            const float sqj = g_sq[j];
            const int   lj  = g_lab[j];
            #pragma unroll
            for (int a = 0; a < 4; a++) {
                float d2 = fmaf(-2.f, acc[a][b], sqi[a] + sqj);
                float dist = d2 > 0.f ? sqrtf(d2) : 0.f;
                if (li[a] == lj) {
                    ap[a] = fmaxf(ap[a], dist);
                } else {
                    an[a] = fminf(an[a], dist);
                }
            }
        }
        __syncthreads();
    }

    // reduce across the 16 threads (tx) that share the same 4 rows.
    // lane = (ty&1)*16 + tx, so xor over {1,2,4,8} stays within the tx group.
    #pragma unroll
    for (int a = 0; a < 4; a++) {
        #pragma unroll
        for (int o = 8; o; o >>= 1) {
            ap[a] = fmaxf(ap[a], __shfl_xor_sync(0xffffffffu, ap[a], o));
            an[a] = fminf(an[a], __shfl_xor_sync(0xffffffffu, an[a], o));
        }
    }
    if (tx == 0) {
        #pragma unroll
        for (int a = 0; a < 4; a++) {
            int r = rowBase + ty * 4 + a;
            // nonnegative floats: int ordering == float ordering
            atomicMax((int*)&g_ap[r], __float_as_int(ap[a]));
            atomicMin((int*)&g_an[r], __float_as_int(an[a]));
        }
    }
}

// ---------------------------------------------------------------------------
// Kernel 3: final scalar loss (single block, deterministic reduction)
// ---------------------------------------------------------------------------
__global__ void loss_kernel(float* __restrict__ out) {
    __shared__ float ssum[256];
    __shared__ int   scnt[256];
    float s = 0.f; int c = 0;
    for (int i = threadIdx.x; i < N; i += 256) {
        float ap = g_ap[i];
        float an = g_an[i];
        if (ap > 0.f && isfinite(an)) {
            c++;
            float v = ap - an + MARGIN;
            s += v > 0.f ? v : 0.f;
        }
    }
    ssum[threadIdx.x] = s;
    scnt[threadIdx.x] = c;
    __syncthreads();
    for (int o = 128; o; o >>= 1) {
        if (threadIdx.x < o) {
            ssum[threadIdx.x] += ssum[threadIdx.x + o];
            scnt[threadIdx.x] += scnt[threadIdx.x + o];
        }
        __syncthreads();
    }
    if (threadIdx.x == 0) {
        int n = scnt[0];
        out[0] = (n > 0) ? (ssum[0] / (float)n) : 0.f;
    }
}

// ---------------------------------------------------------------------------
extern "C" void kernel_launch(void* const* d_in, const int* in_sizes, int n_in,
                              void* d_out, int out_size) {
    const float* F   = (const float*)d_in[0];
    const int*   lab = (const int*)d_in[1];
    float* out = (float*)d_out;

    prep_kernel<<<N, 256>>>(F, lab);
    dim3 grid(N / TI, COLSPLIT);
    dist_mine_kernel<<<grid, 256>>>(F);
    loss_kernel<<<1, 256>>>(out);
}

// round 4
// speedup vs baseline: 4.2390x; 4.2390x over previous
#include <cuda_runtime.h>
#include <cuda_bf16.h>
#include <math.h>
#include <stdint.h>

#define N 4096
#define D 2048
#define MARGIN 0.3f

// ---------------------------------------------------------------------------
// Device globals (no allocation allowed)
// ---------------------------------------------------------------------------
__device__ __nv_bfloat16 g_H[(size_t)N * D];   // hi part of features
__device__ __nv_bfloat16 g_L[(size_t)N * D];   // lo part (residual)
__device__ float g_sq[N];
__device__ int   g_lab[N];
__device__ float g_ap[N];
__device__ float g_an[N];

// ---------------------------------------------------------------------------
// Kernel 1: split fp32 -> bf16 hi/lo, squared norms, init accumulators
// ---------------------------------------------------------------------------
__global__ void prep_kernel(const float* __restrict__ F,
                            const int* __restrict__ lab) {
    int row = blockIdx.x;
    const float4* f4 = reinterpret_cast<const float4*>(F + (size_t)row * D);
    __nv_bfloat162* h2 = reinterpret_cast<__nv_bfloat162*>(g_H + (size_t)row * D);
    __nv_bfloat162* l2 = reinterpret_cast<__nv_bfloat162*>(g_L + (size_t)row * D);
    float s = 0.f;
    for (int k = threadIdx.x; k < D / 4; k += blockDim.x) {
        float4 v = f4[k];
        s += v.x * v.x + v.y * v.y + v.z * v.z + v.w * v.w;
        __nv_bfloat16 hx = __float2bfloat16_rn(v.x);
        __nv_bfloat16 hy = __float2bfloat16_rn(v.y);
        __nv_bfloat16 hz = __float2bfloat16_rn(v.z);
        __nv_bfloat16 hw = __float2bfloat16_rn(v.w);
        __nv_bfloat16 lx = __float2bfloat16_rn(v.x - __bfloat162float(hx));
        __nv_bfloat16 ly = __float2bfloat16_rn(v.y - __bfloat162float(hy));
        __nv_bfloat16 lz = __float2bfloat16_rn(v.z - __bfloat162float(hz));
        __nv_bfloat16 lw = __float2bfloat16_rn(v.w - __bfloat162float(hw));
        h2[k * 2 + 0] = __nv_bfloat162{hx, hy};
        h2[k * 2 + 1] = __nv_bfloat162{hz, hw};
        l2[k * 2 + 0] = __nv_bfloat162{lx, ly};
        l2[k * 2 + 1] = __nv_bfloat162{lz, lw};
    }
    __shared__ float red[8];
    #pragma unroll
    for (int o = 16; o; o >>= 1) s += __shfl_xor_sync(0xffffffffu, s, o);
    if ((threadIdx.x & 31) == 0) red[threadIdx.x >> 5] = s;
    __syncthreads();
    if (threadIdx.x == 0) {
        float t = 0.f;
        #pragma unroll
        for (int w = 0; w < 8; w++) t += red[w];
        g_sq[row]  = t;
        g_lab[row] = lab[row];
        g_ap[row]  = 0.f;
        g_an[row]  = __int_as_float(0x7f800000);
    }
}

// ---------------------------------------------------------------------------
// Kernel 2: mma.sync bf16 Gram tile (128x128) + distance + mining
// G = H.H^T + H.L^T + L.H^T, fp32 accumulate in registers.
// ---------------------------------------------------------------------------
#define TM 128
#define TN 128
#define KCH 64                       // bf16 elements per K chunk
#define NCHUNK (3 * D / KCH)         // 96
#define ROWB 144                     // padded row bytes (128 data + 16 pad)
#define TILEB (TM * ROWB)            // 18432 per tile buffer

#define OFF_A   0                    // 2 buffers
#define OFF_B   (2 * TILEB)          // 2 buffers
#define OFF_RSQ (4 * TILEB)          // float[128]
#define OFF_RLB (OFF_RSQ + 512)     // int[128]
#define OFF_CSQ (OFF_RLB + 512)     // float[128]
#define OFF_CLB (OFF_CSQ + 512)     // int[128]
#define SMEM_BYTES (OFF_CLB + 512)

__device__ __forceinline__ uint32_t smem_u32(const void* p) {
    uint32_t a;
    asm("{ .reg .u64 t; cvta.to.shared.u64 t, %1; cvt.u32.u64 %0, t; }" : "=r"(a) : "l"(p));
    return a;
}
__device__ __forceinline__ void cp16(uint32_t dst, const void* src) {
    asm volatile("cp.async.cg.shared.global [%0], [%1], 16;" :: "r"(dst), "l"(src));
}
__device__ __forceinline__ void cp_commit() {
    asm volatile("cp.async.commit_group;" ::: "memory");
}
__device__ __forceinline__ void ldsm_x4(uint32_t& r0, uint32_t& r1, uint32_t& r2,
                                        uint32_t& r3, uint32_t addr) {
    asm volatile("ldmatrix.sync.aligned.m8n8.x4.shared.b16 {%0,%1,%2,%3}, [%4];"
                 : "=r"(r0), "=r"(r1), "=r"(r2), "=r"(r3) : "r"(addr));
}
__device__ __forceinline__ void mma_bf16(float* c, uint32_t a0, uint32_t a1,
                                         uint32_t a2, uint32_t a3,
                                         uint32_t b0, uint32_t b1) {
    asm volatile("mma.sync.aligned.m16n8k16.row.col.f32.bf16.bf16.f32 "
                 "{%0,%1,%2,%3}, {%4,%5,%6,%7}, {%8,%9}, {%0,%1,%2,%3};"
                 : "+f"(c[0]), "+f"(c[1]), "+f"(c[2]), "+f"(c[3])
                 : "r"(a0), "r"(a1), "r"(a2), "r"(a3), "r"(b0), "r"(b1));
}

__global__ __launch_bounds__(256, 2)
void mma_mine_kernel() {
    extern __shared__ char sb[];
    const uint32_t sbase = smem_u32(sb);
    const int tid  = threadIdx.x;
    const int lane = tid & 31;
    const int wid  = tid >> 5;
    const int wm   = wid >> 1;        // 0..3  (32 rows each)
    const int wn   = wid & 1;         // 0..1  (64 cols each)

    const int rowBase = blockIdx.x * TM;
    const int colBase = blockIdx.y * TN;

    // stage row/col sq + labels
    if (tid < 128) {
        ((float*)(sb + OFF_RSQ))[tid] = g_sq[rowBase + tid];
        ((int*)(sb + OFF_RLB))[tid]   = g_lab[rowBase + tid];
        ((float*)(sb + OFF_CSQ))[tid] = g_sq[colBase + tid];
        ((int*)(sb + OFF_CLB))[tid]   = g_lab[colBase + tid];
    }

    // cp.async load mapping: 1024 16B vectors per tile, 4 per thread
    const int ldR = tid >> 3;         // row (with +32*i)
    const int ldQ = tid & 7;          // 16B slot within 128B row

    // issue loads for chunk c into buffer (c&1)
    auto issue = [&](int c) {
        const int seg = c >> 5;
        const int kc  = (c & 31) * KCH;
        const __nv_bfloat16* __restrict__ Asrc = (seg == 2) ? g_L : g_H;
        const __nv_bfloat16* __restrict__ Bsrc = (seg == 1) ? g_L : g_H;
        const uint32_t aB = sbase + OFF_A + (c & 1) * TILEB;
        const uint32_t bB = sbase + OFF_B + (c & 1) * TILEB;
        #pragma unroll
        for (int i = 0; i < 4; i++) {
            int r = ldR + i * 32;
            cp16(aB + r * ROWB + ldQ * 16,
                 Asrc + (size_t)(rowBase + r) * D + kc + ldQ * 8);
            cp16(bB + r * ROWB + ldQ * 16,
                 Bsrc + (size_t)(colBase + r) * D + kc + ldQ * 8);
        }
        cp_commit();
    };

    // ldmatrix base addresses (per-thread, lane dependent)
    // A: per mi (0..1): mat = lane>>3: rows m (l&15), k half (l>>4)
    uint32_t aOff[2];
    #pragma unroll
    for (int mi = 0; mi < 2; mi++) {
        int r = wm * 32 + mi * 16 + (lane & 15);
        aOff[mi] = sbase + OFF_A + r * ROWB + (lane >> 4) * 16;
    }
    // B: per nt (0..3): mat = lane>>3: n = wn*64 + nt*16 + 8*(mat>=2) + (l&7),
    //    k half = mat&1
    uint32_t bOff[4];
    {
        int mat = lane >> 3;
        #pragma unroll
        for (int nt = 0; nt < 4; nt++) {
            int n = wn * 64 + nt * 16 + ((mat & 2) << 2) + (lane & 7);
            bOff[nt] = sbase + OFF_B + n * ROWB + (mat & 1) * 16;
        }
    }

    float acc[2][8][4];
    #pragma unroll
    for (int mi = 0; mi < 2; mi++)
        #pragma unroll
        for (int ni = 0; ni < 8; ni++)
            #pragma unroll
            for (int r = 0; r < 4; r++) acc[mi][ni][r] = 0.f;

    issue(0);

    for (int c = 0; c < NCHUNK; c++) {
        if (c + 1 < NCHUNK) {
            issue(c + 1);
            asm volatile("cp.async.wait_group 1;" ::: "memory");
        } else {
            asm volatile("cp.async.wait_group 0;" ::: "memory");
        }
        __syncthreads();

        const uint32_t bufAdd = (c & 1) * TILEB;
        #pragma unroll
        for (int ks = 0; ks < 4; ks++) {
            uint32_t a[2][4];
            #pragma unroll
            for (int mi = 0; mi < 2; mi++)
                ldsm_x4(a[mi][0], a[mi][1], a[mi][2], a[mi][3],
                        aOff[mi] + bufAdd + ks * 32);
            uint32_t b[8][2];
            #pragma unroll
            for (int nt = 0; nt < 4; nt++) {
                uint32_t r0, r1, r2, r3;
                ldsm_x4(r0, r1, r2, r3, bOff[nt] + bufAdd + ks * 32);
                b[nt * 2 + 0][0] = r0; b[nt * 2 + 0][1] = r1;
                b[nt * 2 + 1][0] = r2; b[nt * 2 + 1][1] = r3;
            }
            #pragma unroll
            for (int mi = 0; mi < 2; mi++)
                #pragma unroll
                for (int ni = 0; ni < 8; ni++)
                    mma_bf16(acc[mi][ni], a[mi][0], a[mi][1], a[mi][2], a[mi][3],
                             b[ni][0], b[ni][1]);
        }
        __syncthreads();
    }

    // ------------------- epilogue: distance + mining -------------------
    const float* rsq = (const float*)(sb + OFF_RSQ);
    const int*   rlb = (const int*)(sb + OFF_RLB);
    const float* csq = (const float*)(sb + OFF_CSQ);
    const int*   clb = (const int*)(sb + OFF_CLB);

    float apv[2][2], anv[2][2];
    #pragma unroll
    for (int mi = 0; mi < 2; mi++)
        #pragma unroll
        for (int h = 0; h < 2; h++) {
            apv[mi][h] = 0.f;
            anv[mi][h] = __int_as_float(0x7f800000);
        }

    #pragma unroll
    for (int mi = 0; mi < 2; mi++) {
        const int r0 = wm * 32 + mi * 16 + (lane >> 2);
        const float sq0 = rsq[r0],     sq1 = rsq[r0 + 8];
        const int   lb0 = rlb[r0],     lb1 = rlb[r0 + 8];
        #pragma unroll
        for (int ni = 0; ni < 8; ni++) {
            const int jl = wn * 64 + ni * 8 + (lane & 3) * 2;
            #pragma unroll
            for (int e = 0; e < 2; e++) {
                const float sqj = csq[jl + e];
                const int   lj  = clb[jl + e];
                // half 0: rows r0
                {
                    float d2 = fmaf(-2.f, acc[mi][ni][e], sq0 + sqj);
                    float dist = d2 > 0.f ? sqrtf(d2) : 0.f;
                    if (lb0 == lj) apv[mi][0] = fmaxf(apv[mi][0], dist);
                    else           anv[mi][0] = fminf(anv[mi][0], dist);
                }
                // half 1: rows r0+8 (regs 2,3)
                {
                    float d2 = fmaf(-2.f, acc[mi][ni][2 + e], sq1 + sqj);
                    float dist = d2 > 0.f ? sqrtf(d2) : 0.f;
                    if (lb1 == lj) apv[mi][1] = fmaxf(apv[mi][1], dist);
                    else           anv[mi][1] = fminf(anv[mi][1], dist);
                }
            }
        }
    }

    // reduce over the 4 lanes sharing each row (xor 1, 2 keep lane>>2 fixed)
    #pragma unroll
    for (int mi = 0; mi < 2; mi++)
        #pragma unroll
        for (int h = 0; h < 2; h++) {
            #pragma unroll
            for (int o = 1; o <= 2; o <<= 1) {
                apv[mi][h] = fmaxf(apv[mi][h], __shfl_xor_sync(0xffffffffu, apv[mi][h], o));
                anv[mi][h] = fminf(anv[mi][h], __shfl_xor_sync(0xffffffffu, anv[mi][h], o));
            }
        }
    if ((lane & 3) == 0) {
        #pragma unroll
        for (int mi = 0; mi < 2; mi++)
            #pragma unroll
            for (int h = 0; h < 2; h++) {
                int row = rowBase + wm * 32 + mi * 16 + h * 8 + (lane >> 2);
                atomicMax((int*)&g_ap[row], __float_as_int(apv[mi][h]));
                atomicMin((int*)&g_an[row], __float_as_int(anv[mi][h]));
            }
    }
}

// ---------------------------------------------------------------------------
// Kernel 3: final scalar loss
// ---------------------------------------------------------------------------
__global__ void loss_kernel(float* __restrict__ out) {
    __shared__ float ssum[256];
    __shared__ int   scnt[256];
    float s = 0.f; int c = 0;
    for (int i = threadIdx.x; i < N; i += 256) {
        float ap = g_ap[i];
        float an = g_an[i];
        if (ap > 0.f && isfinite(an)) {
            c++;
            float v = ap - an + MARGIN;
            s += v > 0.f ? v : 0.f;
        }
    }
    ssum[threadIdx.x] = s;
    scnt[threadIdx.x] = c;
    __syncthreads();
    for (int o = 128; o; o >>= 1) {
        if (threadIdx.x < o) {
            ssum[threadIdx.x] += ssum[threadIdx.x + o];
            scnt[threadIdx.x] += scnt[threadIdx.x + o];
        }
        __syncthreads();
    }
    if (threadIdx.x == 0) {
        int n = scnt[0];
        out[0] = (n > 0) ? (ssum[0] / (float)n) : 0.f;
    }
}

// ---------------------------------------------------------------------------
extern "C" void kernel_launch(void* const* d_in, const int* in_sizes, int n_in,
                              void* d_out, int out_size) {
    const float* F   = (const float*)d_in[0];
    const int*   lab = (const int*)d_in[1];
    float* out = (float*)d_out;

    cudaFuncSetAttribute(mma_mine_kernel,
                         cudaFuncAttributeMaxDynamicSharedMemorySize, SMEM_BYTES);

    prep_kernel<<<N, 256>>>(F, lab);
    dim3 grid(N / TM, N / TN);
    mma_mine_kernel<<<grid, 256, SMEM_BYTES>>>();
    loss_kernel<<<1, 256>>>(out);
}

// round 5
// speedup vs baseline: 6.8541x; 1.6169x over previous
#include <cuda_runtime.h>
#include <cuda_bf16.h>
#include <math.h>
#include <stdint.h>

#define N 4096
#define D 2048
#define MARGIN 0.3f

// ---------------------------------------------------------------------------
// Device globals (no allocation allowed)
// ---------------------------------------------------------------------------
__device__ __nv_bfloat16 g_H[(size_t)N * D];   // hi part of features
__device__ __nv_bfloat16 g_L[(size_t)N * D];   // lo part (residual)
__device__ float g_sq[N];
__device__ int   g_lab[N];
__device__ float g_ap[N];
__device__ float g_an[N];

// ---------------------------------------------------------------------------
// Kernel 1: split fp32 -> bf16 hi/lo, squared norms, init accumulators
// ---------------------------------------------------------------------------
__global__ void prep_kernel(const float* __restrict__ F,
                            const int* __restrict__ lab) {
    int row = blockIdx.x;
    const float4* f4 = reinterpret_cast<const float4*>(F + (size_t)row * D);
    __nv_bfloat162* h2 = reinterpret_cast<__nv_bfloat162*>(g_H + (size_t)row * D);
    __nv_bfloat162* l2 = reinterpret_cast<__nv_bfloat162*>(g_L + (size_t)row * D);
    float s = 0.f;
    for (int k = threadIdx.x; k < D / 4; k += blockDim.x) {
        float4 v = f4[k];
        s += v.x * v.x + v.y * v.y + v.z * v.z + v.w * v.w;
        __nv_bfloat16 hx = __float2bfloat16_rn(v.x);
        __nv_bfloat16 hy = __float2bfloat16_rn(v.y);
        __nv_bfloat16 hz = __float2bfloat16_rn(v.z);
        __nv_bfloat16 hw = __float2bfloat16_rn(v.w);
        __nv_bfloat16 lx = __float2bfloat16_rn(v.x - __bfloat162float(hx));
        __nv_bfloat16 ly = __float2bfloat16_rn(v.y - __bfloat162float(hy));
        __nv_bfloat16 lz = __float2bfloat16_rn(v.z - __bfloat162float(hz));
        __nv_bfloat16 lw = __float2bfloat16_rn(v.w - __bfloat162float(hw));
        h2[k * 2 + 0] = __nv_bfloat162{hx, hy};
        h2[k * 2 + 1] = __nv_bfloat162{hz, hw};
        l2[k * 2 + 0] = __nv_bfloat162{lx, ly};
        l2[k * 2 + 1] = __nv_bfloat162{lz, lw};
    }
    __shared__ float red[8];
    #pragma unroll
    for (int o = 16; o; o >>= 1) s += __shfl_xor_sync(0xffffffffu, s, o);
    if ((threadIdx.x & 31) == 0) red[threadIdx.x >> 5] = s;
    __syncthreads();
    if (threadIdx.x == 0) {
        float t = 0.f;
        #pragma unroll
        for (int w = 0; w < 8; w++) t += red[w];
        g_sq[row]  = t;
        g_lab[row] = lab[row];
        g_ap[row]  = 0.f;
        g_an[row]  = __int_as_float(0x7f800000);
    }
}

// ---------------------------------------------------------------------------
// Kernel 2: mma.sync bf16 Gram tile (128x128), LOWER TRIANGLE ONLY.
// Off-diagonal tiles mine both directions (rows over cols, cols over rows).
// G = H.H^T + H.L^T + L.H^T, fp32 accumulate in registers.
// ---------------------------------------------------------------------------
#define TM 128
#define TN 128
#define KCH 64                       // bf16 elements per K chunk
#define NCHUNK (3 * D / KCH)         // 96
#define ROWB 144                     // padded row bytes (128 data + 16 pad)
#define TILEB (TM * ROWB)            // 18432 per tile buffer
#define NTILE (N / TM)               // 32
#define NBLK (NTILE * (NTILE + 1) / 2)  // 528

#define OFF_A   0                    // 2 buffers
#define OFF_B   (2 * TILEB)          // 2 buffers
#define OFF_RSQ (4 * TILEB)          // float[128]
#define OFF_RLB (OFF_RSQ + 512)     // int[128]
#define OFF_CSQ (OFF_RLB + 512)     // float[128]
#define OFF_CLB (OFF_CSQ + 512)     // int[128]
#define SMEM_BYTES (OFF_CLB + 512)

__device__ __forceinline__ uint32_t smem_u32(const void* p) {
    uint32_t a;
    asm("{ .reg .u64 t; cvta.to.shared.u64 t, %1; cvt.u32.u64 %0, t; }" : "=r"(a) : "l"(p));
    return a;
}
__device__ __forceinline__ void cp16(uint32_t dst, const void* src) {
    asm volatile("cp.async.cg.shared.global [%0], [%1], 16;" :: "r"(dst), "l"(src));
}
__device__ __forceinline__ void cp_commit() {
    asm volatile("cp.async.commit_group;" ::: "memory");
}
__device__ __forceinline__ void ldsm_x4(uint32_t& r0, uint32_t& r1, uint32_t& r2,
                                        uint32_t& r3, uint32_t addr) {
    asm volatile("ldmatrix.sync.aligned.m8n8.x4.shared.b16 {%0,%1,%2,%3}, [%4];"
                 : "=r"(r0), "=r"(r1), "=r"(r2), "=r"(r3) : "r"(addr));
}
__device__ __forceinline__ void mma_bf16(float* c, uint32_t a0, uint32_t a1,
                                         uint32_t a2, uint32_t a3,
                                         uint32_t b0, uint32_t b1) {
    asm volatile("mma.sync.aligned.m16n8k16.row.col.f32.bf16.bf16.f32 "
                 "{%0,%1,%2,%3}, {%4,%5,%6,%7}, {%8,%9}, {%0,%1,%2,%3};"
                 : "+f"(c[0]), "+f"(c[1]), "+f"(c[2]), "+f"(c[3])
                 : "r"(a0), "r"(a1), "r"(a2), "r"(a3), "r"(b0), "r"(b1));
}

__global__ __launch_bounds__(256, 2)
void mma_mine_kernel() {
    extern __shared__ char sb[];
    const uint32_t sbase = smem_u32(sb);
    const int tid  = threadIdx.x;
    const int lane = tid & 31;
    const int wid  = tid >> 5;
    const int wm   = wid >> 1;        // 0..3  (32 rows each)
    const int wn   = wid & 1;         // 0..1  (64 cols each)

    // decode lower-triangular tile index: bi >= bj
    int t = blockIdx.x;
    int bi = (int)floorf((sqrtf(8.0f * (float)t + 1.0f) - 1.0f) * 0.5f);
    while ((bi + 1) * (bi + 2) / 2 <= t) ++bi;
    while (bi * (bi + 1) / 2 > t) --bi;
    int bj = t - bi * (bi + 1) / 2;

    const int rowBase = bi * TM;
    const int colBase = bj * TN;
    const bool offdiag = (bi != bj);

    // stage row/col sq + labels
    if (tid < 128) {
        ((float*)(sb + OFF_RSQ))[tid] = g_sq[rowBase + tid];
        ((int*)(sb + OFF_RLB))[tid]   = g_lab[rowBase + tid];
        ((float*)(sb + OFF_CSQ))[tid] = g_sq[colBase + tid];
        ((int*)(sb + OFF_CLB))[tid]   = g_lab[colBase + tid];
    }

    // cp.async load mapping: 1024 16B vectors per tile, 4 per thread
    const int ldR = tid >> 3;         // row (with +32*i)
    const int ldQ = tid & 7;          // 16B slot within 128B row

    auto issue = [&](int c) {
        const int seg = c >> 5;
        const int kc  = (c & 31) * KCH;
        const __nv_bfloat16* __restrict__ Asrc = (seg == 2) ? g_L : g_H;
        const __nv_bfloat16* __restrict__ Bsrc = (seg == 1) ? g_L : g_H;
        const uint32_t aB = sbase + OFF_A + (c & 1) * TILEB;
        const uint32_t bB = sbase + OFF_B + (c & 1) * TILEB;
        #pragma unroll
        for (int i = 0; i < 4; i++) {
            int r = ldR + i * 32;
            cp16(aB + r * ROWB + ldQ * 16,
                 Asrc + (size_t)(rowBase + r) * D + kc + ldQ * 8);
            cp16(bB + r * ROWB + ldQ * 16,
                 Bsrc + (size_t)(colBase + r) * D + kc + ldQ * 8);
        }
        cp_commit();
    };

    // ldmatrix base addresses
    uint32_t aOff[2];
    #pragma unroll
    for (int mi = 0; mi < 2; mi++) {
        int r = wm * 32 + mi * 16 + (lane & 15);
        aOff[mi] = sbase + OFF_A + r * ROWB + (lane >> 4) * 16;
    }
    uint32_t bOff[4];
    {
        int mat = lane >> 3;
        #pragma unroll
        for (int nt = 0; nt < 4; nt++) {
            int n = wn * 64 + nt * 16 + ((mat & 2) << 2) + (lane & 7);
            bOff[nt] = sbase + OFF_B + n * ROWB + (mat & 1) * 16;
        }
    }

    float acc[2][8][4];
    #pragma unroll
    for (int mi = 0; mi < 2; mi++)
        #pragma unroll
        for (int ni = 0; ni < 8; ni++)
            #pragma unroll
            for (int r = 0; r < 4; r++) acc[mi][ni][r] = 0.f;

    issue(0);

    for (int c = 0; c < NCHUNK; c++) {
        if (c + 1 < NCHUNK) {
            issue(c + 1);
            asm volatile("cp.async.wait_group 1;" ::: "memory");
        } else {
            asm volatile("cp.async.wait_group 0;" ::: "memory");
        }
        __syncthreads();

        const uint32_t bufAdd = (c & 1) * TILEB;
        #pragma unroll
        for (int ks = 0; ks < 4; ks++) {
            uint32_t a[2][4];
            #pragma unroll
            for (int mi = 0; mi < 2; mi++)
                ldsm_x4(a[mi][0], a[mi][1], a[mi][2], a[mi][3],
                        aOff[mi] + bufAdd + ks * 32);
            uint32_t b[8][2];
            #pragma unroll
            for (int nt = 0; nt < 4; nt++) {
                uint32_t r0, r1, r2, r3;
                ldsm_x4(r0, r1, r2, r3, bOff[nt] + bufAdd + ks * 32);
                b[nt * 2 + 0][0] = r0; b[nt * 2 + 0][1] = r1;
                b[nt * 2 + 1][0] = r2; b[nt * 2 + 1][1] = r3;
            }
            #pragma unroll
            for (int mi = 0; mi < 2; mi++)
                #pragma unroll
                for (int ni = 0; ni < 8; ni++)
                    mma_bf16(acc[mi][ni], a[mi][0], a[mi][1], a[mi][2], a[mi][3],
                             b[ni][0], b[ni][1]);
        }
        __syncthreads();
    }

    // ------------------- epilogue: distance + two-way mining -------------------
    const float* rsq = (const float*)(sb + OFF_RSQ);
    const int*   rlb = (const int*)(sb + OFF_RLB);
    const float* csq = (const float*)(sb + OFF_CSQ);
    const int*   clb = (const int*)(sb + OFF_CLB);

    const float INF = __int_as_float(0x7f800000);

    // row-side state & per-thread row attrs
    float apv[2][2], anv[2][2];
    float sqr[2][2]; int lbr[2][2];
    #pragma unroll
    for (int mi = 0; mi < 2; mi++)
        #pragma unroll
        for (int h = 0; h < 2; h++) {
            apv[mi][h] = 0.f;
            anv[mi][h] = INF;
            int r = wm * 32 + mi * 16 + h * 8 + (lane >> 2);
            sqr[mi][h] = rsq[r];
            lbr[mi][h] = rlb[r];
        }

    #pragma unroll
    for (int ni = 0; ni < 8; ni++) {
        const int jl = wn * 64 + ni * 8 + (lane & 3) * 2;
        float cap[2] = {0.f, 0.f};
        float can[2] = {INF, INF};
        #pragma unroll
        for (int e = 0; e < 2; e++) {
            const float sqj = csq[jl + e];
            const int   lj  = clb[jl + e];
            #pragma unroll
            for (int mi = 0; mi < 2; mi++)
                #pragma unroll
                for (int h = 0; h < 2; h++) {
                    float g = acc[mi][ni][h * 2 + e];
                    float d2 = fmaf(-2.f, g, sqr[mi][h] + sqj);
                    float dist = d2 > 0.f ? sqrtf(d2) : 0.f;
                    if (lbr[mi][h] == lj) {
                        apv[mi][h] = fmaxf(apv[mi][h], dist);
                        cap[e] = fmaxf(cap[e], dist);
                    } else {
                        anv[mi][h] = fminf(anv[mi][h], dist);
                        can[e] = fminf(can[e], dist);
                    }
                }
        }
        if (offdiag) {
            // column mining: reduce over lane>>2 groups (same lane&3 = same col)
            #pragma unroll
            for (int e = 0; e < 2; e++) {
                #pragma unroll
                for (int o = 4; o <= 16; o <<= 1) {
                    cap[e] = fmaxf(cap[e], __shfl_xor_sync(0xffffffffu, cap[e], o));
                    can[e] = fminf(can[e], __shfl_xor_sync(0xffffffffu, can[e], o));
                }
                if (lane < 4) {
                    int col = colBase + wn * 64 + ni * 8 + lane * 2 + e;
                    atomicMax((int*)&g_ap[col], __float_as_int(cap[e]));
                    atomicMin((int*)&g_an[col], __float_as_int(can[e]));
                }
            }
        }
    }

    // row-side reduction over 4 lanes sharing each row
    #pragma unroll
    for (int mi = 0; mi < 2; mi++)
        #pragma unroll
        for (int h = 0; h < 2; h++) {
            #pragma unroll
            for (int o = 1; o <= 2; o <<= 1) {
                apv[mi][h] = fmaxf(apv[mi][h], __shfl_xor_sync(0xffffffffu, apv[mi][h], o));
                anv[mi][h] = fminf(anv[mi][h], __shfl_xor_sync(0xffffffffu, anv[mi][h], o));
            }
        }
    if ((lane & 3) == 0) {
        #pragma unroll
        for (int mi = 0; mi < 2; mi++)
            #pragma unroll
            for (int h = 0; h < 2; h++) {
                int row = rowBase + wm * 32 + mi * 16 + h * 8 + (lane >> 2);
                atomicMax((int*)&g_ap[row], __float_as_int(apv[mi][h]));
                atomicMin((int*)&g_an[row], __float_as_int(anv[mi][h]));
            }
    }
}

// ---------------------------------------------------------------------------
// Kernel 3: final scalar loss
// ---------------------------------------------------------------------------
__global__ void loss_kernel(float* __restrict__ out) {
    __shared__ float ssum[256];
    __shared__ int   scnt[256];
    float s = 0.f; int c = 0;
    for (int i = threadIdx.x; i < N; i += 256) {
        float ap = g_ap[i];
        float an = g_an[i];
        if (ap > 0.f && isfinite(an)) {
            c++;
            float v = ap - an + MARGIN;
            s += v > 0.f ? v : 0.f;
        }
    }
    ssum[threadIdx.x] = s;
    scnt[threadIdx.x] = c;
    __syncthreads();
    for (int o = 128; o; o >>= 1) {
        if (threadIdx.x < o) {
            ssum[threadIdx.x] += ssum[threadIdx.x + o];
            scnt[threadIdx.x] += scnt[threadIdx.x + o];
        }
        __syncthreads();
    }
    if (threadIdx.x == 0) {
        int n = scnt[0];
        out[0] = (n > 0) ? (ssum[0] / (float)n) : 0.f;
    }
}

// ---------------------------------------------------------------------------
extern "C" void kernel_launch(void* const* d_in, const int* in_sizes, int n_in,
                              void* d_out, int out_size) {
    const float* F   = (const float*)d_in[0];
    const int*   lab = (const int*)d_in[1];
    float* out = (float*)d_out;

    cudaFuncSetAttribute(mma_mine_kernel,
                         cudaFuncAttributeMaxDynamicSharedMemorySize, SMEM_BYTES);

    prep_kernel<<<N, 256>>>(F, lab);
    mma_mine_kernel<<<NBLK, 256, SMEM_BYTES>>>();
    loss_kernel<<<1, 256>>>(out);
}

// round 6
// speedup vs baseline: 9.9004x; 1.4444x over previous
#include <cuda_runtime.h>
#include <cuda_bf16.h>
#include <math.h>
#include <stdint.h>

#define N 4096
#define D 2048
#define MARGIN 0.3f

// ---------------------------------------------------------------------------
// Device globals (no allocation allowed)
// ---------------------------------------------------------------------------
__device__ float g_T[(size_t)N * D];   // tf32-rounded copy of features
__device__ float g_sq[N];
__device__ int   g_lab[N];
__device__ float g_ap[N];
__device__ float g_an[N];

__device__ __forceinline__ float to_tf32(float x) {
    float r;
    asm("cvt.rna.tf32.f32 %0, %1;" : "=f"(r) : "f"(x));
    return r;
}

// ---------------------------------------------------------------------------
// Kernel 1: round fp32 -> tf32 copy, squared norms, init accumulators
// ---------------------------------------------------------------------------
__global__ void prep_kernel(const float* __restrict__ F,
                            const int* __restrict__ lab) {
    int row = blockIdx.x;
    const float4* f4 = reinterpret_cast<const float4*>(F + (size_t)row * D);
    float4* t4 = reinterpret_cast<float4*>(g_T + (size_t)row * D);
    float s = 0.f;
    for (int k = threadIdx.x; k < D / 4; k += blockDim.x) {
        float4 v = f4[k];
        s += v.x * v.x + v.y * v.y + v.z * v.z + v.w * v.w;
        float4 t;
        t.x = to_tf32(v.x); t.y = to_tf32(v.y);
        t.z = to_tf32(v.z); t.w = to_tf32(v.w);
        t4[k] = t;
    }
    __shared__ float red[8];
    #pragma unroll
    for (int o = 16; o; o >>= 1) s += __shfl_xor_sync(0xffffffffu, s, o);
    if ((threadIdx.x & 31) == 0) red[threadIdx.x >> 5] = s;
    __syncthreads();
    if (threadIdx.x == 0) {
        float t = 0.f;
        #pragma unroll
        for (int w = 0; w < 8; w++) t += red[w];
        g_sq[row]  = t;
        g_lab[row] = lab[row];
        g_ap[row]  = 0.f;
        g_an[row]  = __int_as_float(0x7f800000);
    }
}

// ---------------------------------------------------------------------------
// Kernel 2: mma.sync TF32 Gram tile (128x128), LOWER TRIANGLE ONLY.
// Off-diagonal tiles mine both directions. Single pass, fp32 accumulate.
// ---------------------------------------------------------------------------
#define TM 128
#define TN 128
#define KCH 32                       // tf32 elements per K chunk (=128B/row)
#define NCHUNK (D / KCH)             // 64
#define ROWB 144                     // padded row bytes (128 data + 16 pad)
#define TILEB (TM * ROWB)            // 18432 per tile buffer
#define NTILE (N / TM)               // 32
#define NBLK (NTILE * (NTILE + 1) / 2)  // 528

#define OFF_A   0                    // 2 buffers
#define OFF_B   (2 * TILEB)          // 2 buffers
#define OFF_RSQ (4 * TILEB)          // float[128]
#define OFF_RLB (OFF_RSQ + 512)     // int[128]
#define OFF_CSQ (OFF_RLB + 512)     // float[128]
#define OFF_CLB (OFF_CSQ + 512)     // int[128]
#define SMEM_BYTES (OFF_CLB + 512)

__device__ __forceinline__ uint32_t smem_u32(const void* p) {
    uint32_t a;
    asm("{ .reg .u64 t; cvta.to.shared.u64 t, %1; cvt.u32.u64 %0, t; }" : "=r"(a) : "l"(p));
    return a;
}
__device__ __forceinline__ void cp16(uint32_t dst, const void* src) {
    asm volatile("cp.async.cg.shared.global [%0], [%1], 16;" :: "r"(dst), "l"(src));
}
__device__ __forceinline__ void cp_commit() {
    asm volatile("cp.async.commit_group;" ::: "memory");
}
__device__ __forceinline__ void ldsm_x4(uint32_t& r0, uint32_t& r1, uint32_t& r2,
                                        uint32_t& r3, uint32_t addr) {
    asm volatile("ldmatrix.sync.aligned.m8n8.x4.shared.b16 {%0,%1,%2,%3}, [%4];"
                 : "=r"(r0), "=r"(r1), "=r"(r2), "=r"(r3) : "r"(addr));
}
// m16n8k8 tf32: same fragment register shape as m16n8k16 bf16
__device__ __forceinline__ void mma_tf32(float* c, uint32_t a0, uint32_t a1,
                                         uint32_t a2, uint32_t a3,
                                         uint32_t b0, uint32_t b1) {
    asm volatile("mma.sync.aligned.m16n8k8.row.col.f32.tf32.tf32.f32 "
                 "{%0,%1,%2,%3}, {%4,%5,%6,%7}, {%8,%9}, {%0,%1,%2,%3};"
                 : "+f"(c[0]), "+f"(c[1]), "+f"(c[2]), "+f"(c[3])
                 : "r"(a0), "r"(a1), "r"(a2), "r"(a3), "r"(b0), "r"(b1));
}

__global__ __launch_bounds__(256, 2)
void mma_mine_kernel() {
    extern __shared__ char sb[];
    const uint32_t sbase = smem_u32(sb);
    const int tid  = threadIdx.x;
    const int lane = tid & 31;
    const int wid  = tid >> 5;
    const int wm   = wid >> 1;        // 0..3  (32 rows each)
    const int wn   = wid & 1;         // 0..1  (64 cols each)

    // decode lower-triangular tile index: bi >= bj
    int t = blockIdx.x;
    int bi = (int)floorf((sqrtf(8.0f * (float)t + 1.0f) - 1.0f) * 0.5f);
    while ((bi + 1) * (bi + 2) / 2 <= t) ++bi;
    while (bi * (bi + 1) / 2 > t) --bi;
    int bj = t - bi * (bi + 1) / 2;

    const int rowBase = bi * TM;
    const int colBase = bj * TN;
    const bool offdiag = (bi != bj);

    // stage row/col sq + labels
    if (tid < 128) {
        ((float*)(sb + OFF_RSQ))[tid] = g_sq[rowBase + tid];
        ((int*)(sb + OFF_RLB))[tid]   = g_lab[rowBase + tid];
        ((float*)(sb + OFF_CSQ))[tid] = g_sq[colBase + tid];
        ((int*)(sb + OFF_CLB))[tid]   = g_lab[colBase + tid];
    }

    // cp.async load mapping: 1024 16B vectors per tile, 4 per thread
    const int ldR = tid >> 3;         // row (with +32*i)
    const int ldQ = tid & 7;          // 16B slot within 128B row

    auto issue = [&](int c) {
        const int kc = c * KCH;
        const uint32_t aB = sbase + OFF_A + (c & 1) * TILEB;
        const uint32_t bB = sbase + OFF_B + (c & 1) * TILEB;
        #pragma unroll
        for (int i = 0; i < 4; i++) {
            int r = ldR + i * 32;
            cp16(aB + r * ROWB + ldQ * 16,
                 g_T + (size_t)(rowBase + r) * D + kc + ldQ * 4);
            cp16(bB + r * ROWB + ldQ * 16,
                 g_T + (size_t)(colBase + r) * D + kc + ldQ * 4);
        }
        cp_commit();
    };

    // ldmatrix base addresses (same mapping as bf16; 16B = 4 tf32)
    uint32_t aOff[2];
    #pragma unroll
    for (int mi = 0; mi < 2; mi++) {
        int r = wm * 32 + mi * 16 + (lane & 15);
        aOff[mi] = sbase + OFF_A + r * ROWB + (lane >> 4) * 16;
    }
    uint32_t bOff[4];
    {
        int mat = lane >> 3;
        #pragma unroll
        for (int nt = 0; nt < 4; nt++) {
            int n = wn * 64 + nt * 16 + ((mat & 2) << 2) + (lane & 7);
            bOff[nt] = sbase + OFF_B + n * ROWB + (mat & 1) * 16;
        }
    }

    float acc[2][8][4];
    #pragma unroll
    for (int mi = 0; mi < 2; mi++)
        #pragma unroll
        for (int ni = 0; ni < 8; ni++)
            #pragma unroll
            for (int r = 0; r < 4; r++) acc[mi][ni][r] = 0.f;

    issue(0);

    for (int c = 0; c < NCHUNK; c++) {
        if (c + 1 < NCHUNK) {
            issue(c + 1);
            asm volatile("cp.async.wait_group 1;" ::: "memory");
        } else {
            asm volatile("cp.async.wait_group 0;" ::: "memory");
        }
        __syncthreads();

        const uint32_t bufAdd = (c & 1) * TILEB;
        #pragma unroll
        for (int ks = 0; ks < 4; ks++) {   // 4 x k8 = 32 k per chunk
            uint32_t a[2][4];
            #pragma unroll
            for (int mi = 0; mi < 2; mi++)
                ldsm_x4(a[mi][0], a[mi][1], a[mi][2], a[mi][3],
                        aOff[mi] + bufAdd + ks * 32);
            uint32_t b[8][2];
            #pragma unroll
            for (int nt = 0; nt < 4; nt++) {
                uint32_t r0, r1, r2, r3;
                ldsm_x4(r0, r1, r2, r3, bOff[nt] + bufAdd + ks * 32);
                b[nt * 2 + 0][0] = r0; b[nt * 2 + 0][1] = r1;
                b[nt * 2 + 1][0] = r2; b[nt * 2 + 1][1] = r3;
            }
            #pragma unroll
            for (int mi = 0; mi < 2; mi++)
                #pragma unroll
                for (int ni = 0; ni < 8; ni++)
                    mma_tf32(acc[mi][ni], a[mi][0], a[mi][1], a[mi][2], a[mi][3],
                             b[ni][0], b[ni][1]);
        }
        __syncthreads();
    }

    // ------------------- epilogue: distance + two-way mining -------------------
    const float* rsq = (const float*)(sb + OFF_RSQ);
    const int*   rlb = (const int*)(sb + OFF_RLB);
    const float* csq = (const float*)(sb + OFF_CSQ);
    const int*   clb = (const int*)(sb + OFF_CLB);

    const float INF = __int_as_float(0x7f800000);

    float apv[2][2], anv[2][2];
    float sqr[2][2]; int lbr[2][2];
    #pragma unroll
    for (int mi = 0; mi < 2; mi++)
        #pragma unroll
        for (int h = 0; h < 2; h++) {
            apv[mi][h] = 0.f;
            anv[mi][h] = INF;
            int r = wm * 32 + mi * 16 + h * 8 + (lane >> 2);
            sqr[mi][h] = rsq[r];
            lbr[mi][h] = rlb[r];
        }

    #pragma unroll
    for (int ni = 0; ni < 8; ni++) {
        const int jl = wn * 64 + ni * 8 + (lane & 3) * 2;
        float cap[2] = {0.f, 0.f};
        float can[2] = {INF, INF};
        #pragma unroll
        for (int e = 0; e < 2; e++) {
            const float sqj = csq[jl + e];
            const int   lj  = clb[jl + e];
            #pragma unroll
            for (int mi = 0; mi < 2; mi++)
                #pragma unroll
                for (int h = 0; h < 2; h++) {
                    float g = acc[mi][ni][h * 2 + e];
                    float d2 = fmaf(-2.f, g, sqr[mi][h] + sqj);
                    float dist = d2 > 0.f ? sqrtf(d2) : 0.f;
                    if (lbr[mi][h] == lj) {
                        apv[mi][h] = fmaxf(apv[mi][h], dist);
                        cap[e] = fmaxf(cap[e], dist);
                    } else {
                        anv[mi][h] = fminf(anv[mi][h], dist);
                        can[e] = fminf(can[e], dist);
                    }
                }
        }
        if (offdiag) {
            // column mining: reduce over lane>>2 groups (same lane&3 = same col)
            #pragma unroll
            for (int e = 0; e < 2; e++) {
                #pragma unroll
                for (int o = 4; o <= 16; o <<= 1) {
                    cap[e] = fmaxf(cap[e], __shfl_xor_sync(0xffffffffu, cap[e], o));
                    can[e] = fminf(can[e], __shfl_xor_sync(0xffffffffu, can[e], o));
                }
                if (lane < 4) {
                    int col = colBase + wn * 64 + ni * 8 + lane * 2 + e;
                    atomicMax((int*)&g_ap[col], __float_as_int(cap[e]));
                    atomicMin((int*)&g_an[col], __float_as_int(can[e]));
                }
            }
        }
    }

    // row-side reduction over 4 lanes sharing each row
    #pragma unroll
    for (int mi = 0; mi < 2; mi++)
        #pragma unroll
        for (int h = 0; h < 2; h++) {
            #pragma unroll
            for (int o = 1; o <= 2; o <<= 1) {
                apv[mi][h] = fmaxf(apv[mi][h], __shfl_xor_sync(0xffffffffu, apv[mi][h], o));
                anv[mi][h] = fminf(anv[mi][h], __shfl_xor_sync(0xffffffffu, anv[mi][h], o));
            }
        }
    if ((lane & 3) == 0) {
        #pragma unroll
        for (int mi = 0; mi < 2; mi++)
            #pragma unroll
            for (int h = 0; h < 2; h++) {
                int row = rowBase + wm * 32 + mi * 16 + h * 8 + (lane >> 2);
                atomicMax((int*)&g_ap[row], __float_as_int(apv[mi][h]));
                atomicMin((int*)&g_an[row], __float_as_int(anv[mi][h]));
            }
    }
}

// ---------------------------------------------------------------------------
// Kernel 3: final scalar loss
// ---------------------------------------------------------------------------
__global__ void loss_kernel(float* __restrict__ out) {
    __shared__ float ssum[256];
    __shared__ int   scnt[256];
    float s = 0.f; int c = 0;
    for (int i = threadIdx.x; i < N; i += 256) {
        float ap = g_ap[i];
        float an = g_an[i];
        if (ap > 0.f && isfinite(an)) {
            c++;
            float v = ap - an + MARGIN;
            s += v > 0.f ? v : 0.f;
        }
    }
    ssum[threadIdx.x] = s;
    scnt[threadIdx.x] = c;
    __syncthreads();
    for (int o = 128; o; o >>= 1) {
        if (threadIdx.x < o) {
            ssum[threadIdx.x] += ssum[threadIdx.x + o];
            scnt[threadIdx.x] += scnt[threadIdx.x + o];
        }
        __syncthreads();
    }
    if (threadIdx.x == 0) {
        int n = scnt[0];
        out[0] = (n > 0) ? (ssum[0] / (float)n) : 0.f;
    }
}

// ---------------------------------------------------------------------------
extern "C" void kernel_launch(void* const* d_in, const int* in_sizes, int n_in,
                              void* d_out, int out_size) {
    const float* F   = (const float*)d_in[0];
    const int*   lab = (const int*)d_in[1];
    float* out = (float*)d_out;

    cudaFuncSetAttribute(mma_mine_kernel,
                         cudaFuncAttributeMaxDynamicSharedMemorySize, SMEM_BYTES);

    prep_kernel<<<N, 256>>>(F, lab);
    mma_mine_kernel<<<NBLK, 256, SMEM_BYTES>>>();
    loss_kernel<<<1, 256>>>(out);
}

// round 7
// speedup vs baseline: 17.5639x; 1.7741x over previous
#include <cuda_runtime.h>
#include <cuda_fp16.h>
#include <math.h>
#include <stdint.h>

#define N 4096
#define D 2048
#define MARGIN 0.3f

// ---------------------------------------------------------------------------
// Device globals (no allocation allowed)
// ---------------------------------------------------------------------------
__device__ __half g_Hf[(size_t)N * D];   // fp16-rounded copy of features
__device__ float g_sq[N];
__device__ int   g_lab[N];
__device__ float g_ap[N];
__device__ float g_an[N];

// ---------------------------------------------------------------------------
// Kernel 1: round fp32 -> fp16 copy, squared norms (fp32), init accumulators
// ---------------------------------------------------------------------------
__global__ void prep_kernel(const float* __restrict__ F,
                            const int* __restrict__ lab) {
    int row = blockIdx.x;
    const float4* f4 = reinterpret_cast<const float4*>(F + (size_t)row * D);
    __half2* h2 = reinterpret_cast<__half2*>(g_Hf + (size_t)row * D);
    float s = 0.f;
    for (int k = threadIdx.x; k < D / 4; k += blockDim.x) {
        float4 v = f4[k];
        s += v.x * v.x + v.y * v.y + v.z * v.z + v.w * v.w;
        h2[k * 2 + 0] = __floats2half2_rn(v.x, v.y);
        h2[k * 2 + 1] = __floats2half2_rn(v.z, v.w);
    }
    __shared__ float red[8];
    #pragma unroll
    for (int o = 16; o; o >>= 1) s += __shfl_xor_sync(0xffffffffu, s, o);
    if ((threadIdx.x & 31) == 0) red[threadIdx.x >> 5] = s;
    __syncthreads();
    if (threadIdx.x == 0) {
        float t = 0.f;
        #pragma unroll
        for (int w = 0; w < 8; w++) t += red[w];
        g_sq[row]  = t;
        g_lab[row] = lab[row];
        g_ap[row]  = 0.f;
        g_an[row]  = __int_as_float(0x7f800000);
    }
}

// ---------------------------------------------------------------------------
// Kernel 2: mma.sync fp16 Gram tile (128x128), LOWER TRIANGLE ONLY.
// Off-diagonal tiles mine both directions. Single pass, fp32 accumulate.
// ---------------------------------------------------------------------------
#define TM 128
#define TN 128
#define KCH 64                       // fp16 elements per K chunk (=128B/row)
#define NCHUNK (D / KCH)             // 32
#define ROWB 144                     // padded row bytes (128 data + 16 pad)
#define TILEB (TM * ROWB)            // 18432 per tile buffer
#define NTILE (N / TM)               // 32
#define NBLK (NTILE * (NTILE + 1) / 2)  // 528

#define OFF_A   0                    // 2 buffers
#define OFF_B   (2 * TILEB)          // 2 buffers
#define OFF_RSQ (4 * TILEB)          // float[128]
#define OFF_RLB (OFF_RSQ + 512)     // int[128]
#define OFF_CSQ (OFF_RLB + 512)     // float[128]
#define OFF_CLB (OFF_CSQ + 512)     // int[128]
#define SMEM_BYTES (OFF_CLB + 512)

__device__ __forceinline__ uint32_t smem_u32(const void* p) {
    uint32_t a;
    asm("{ .reg .u64 t; cvta.to.shared.u64 t, %1; cvt.u32.u64 %0, t; }" : "=r"(a) : "l"(p));
    return a;
}
__device__ __forceinline__ void cp16(uint32_t dst, const void* src) {
    asm volatile("cp.async.cg.shared.global [%0], [%1], 16;" :: "r"(dst), "l"(src));
}
__device__ __forceinline__ void cp_commit() {
    asm volatile("cp.async.commit_group;" ::: "memory");
}
__device__ __forceinline__ void ldsm_x4(uint32_t& r0, uint32_t& r1, uint32_t& r2,
                                        uint32_t& r3, uint32_t addr) {
    asm volatile("ldmatrix.sync.aligned.m8n8.x4.shared.b16 {%0,%1,%2,%3}, [%4];"
                 : "=r"(r0), "=r"(r1), "=r"(r2), "=r"(r3) : "r"(addr));
}
__device__ __forceinline__ void mma_f16(float* c, uint32_t a0, uint32_t a1,
                                        uint32_t a2, uint32_t a3,
                                        uint32_t b0, uint32_t b1) {
    asm volatile("mma.sync.aligned.m16n8k16.row.col.f32.f16.f16.f32 "
                 "{%0,%1,%2,%3}, {%4,%5,%6,%7}, {%8,%9}, {%0,%1,%2,%3};"
                 : "+f"(c[0]), "+f"(c[1]), "+f"(c[2]), "+f"(c[3])
                 : "r"(a0), "r"(a1), "r"(a2), "r"(a3), "r"(b0), "r"(b1));
}

__global__ __launch_bounds__(256, 2)
void mma_mine_kernel() {
    extern __shared__ char sb[];
    const uint32_t sbase = smem_u32(sb);
    const int tid  = threadIdx.x;
    const int lane = tid & 31;
    const int wid  = tid >> 5;
    const int wm   = wid >> 1;        // 0..3  (32 rows each)
    const int wn   = wid & 1;         // 0..1  (64 cols each)

    // decode lower-triangular tile index: bi >= bj
    int t = blockIdx.x;
    int bi = (int)floorf((sqrtf(8.0f * (float)t + 1.0f) - 1.0f) * 0.5f);
    while ((bi + 1) * (bi + 2) / 2 <= t) ++bi;
    while (bi * (bi + 1) / 2 > t) --bi;
    int bj = t - bi * (bi + 1) / 2;

    const int rowBase = bi * TM;
    const int colBase = bj * TN;
    const bool offdiag = (bi != bj);

    // stage row/col sq + labels
    if (tid < 128) {
        ((float*)(sb + OFF_RSQ))[tid] = g_sq[rowBase + tid];
        ((int*)(sb + OFF_RLB))[tid]   = g_lab[rowBase + tid];
        ((float*)(sb + OFF_CSQ))[tid] = g_sq[colBase + tid];
        ((int*)(sb + OFF_CLB))[tid]   = g_lab[colBase + tid];
    }

    // cp.async load mapping: 1024 16B vectors per tile, 4 per thread
    const int ldR = tid >> 3;         // row (with +32*i)
    const int ldQ = tid & 7;          // 16B slot within 128B row

    auto issue = [&](int c) {
        const int kc = c * KCH;
        const uint32_t aB = sbase + OFF_A + (c & 1) * TILEB;
        const uint32_t bB = sbase + OFF_B + (c & 1) * TILEB;
        #pragma unroll
        for (int i = 0; i < 4; i++) {
            int r = ldR + i * 32;
            cp16(aB + r * ROWB + ldQ * 16,
                 g_Hf + (size_t)(rowBase + r) * D + kc + ldQ * 8);
            cp16(bB + r * ROWB + ldQ * 16,
                 g_Hf + (size_t)(colBase + r) * D + kc + ldQ * 8);
        }
        cp_commit();
    };

    // ldmatrix base addresses
    uint32_t aOff[2];
    #pragma unroll
    for (int mi = 0; mi < 2; mi++) {
        int r = wm * 32 + mi * 16 + (lane & 15);
        aOff[mi] = sbase + OFF_A + r * ROWB + (lane >> 4) * 16;
    }
    uint32_t bOff[4];
    {
        int mat = lane >> 3;
        #pragma unroll
        for (int nt = 0; nt < 4; nt++) {
            int n = wn * 64 + nt * 16 + ((mat & 2) << 2) + (lane & 7);
            bOff[nt] = sbase + OFF_B + n * ROWB + (mat & 1) * 16;
        }
    }

    float acc[2][8][4];
    #pragma unroll
    for (int mi = 0; mi < 2; mi++)
        #pragma unroll
        for (int ni = 0; ni < 8; ni++)
            #pragma unroll
            for (int r = 0; r < 4; r++) acc[mi][ni][r] = 0.f;

    issue(0);

    for (int c = 0; c < NCHUNK; c++) {
        if (c + 1 < NCHUNK) {
            issue(c + 1);
            asm volatile("cp.async.wait_group 1;" ::: "memory");
        } else {
            asm volatile("cp.async.wait_group 0;" ::: "memory");
        }
        __syncthreads();

        const uint32_t bufAdd = (c & 1) * TILEB;
        #pragma unroll
        for (int ks = 0; ks < 4; ks++) {   // 4 x k16 = 64 k per chunk
            uint32_t a[2][4];
            #pragma unroll
            for (int mi = 0; mi < 2; mi++)
                ldsm_x4(a[mi][0], a[mi][1], a[mi][2], a[mi][3],
                        aOff[mi] + bufAdd + ks * 32);
            uint32_t b[8][2];
            #pragma unroll
            for (int nt = 0; nt < 4; nt++) {
                uint32_t r0, r1, r2, r3;
                ldsm_x4(r0, r1, r2, r3, bOff[nt] + bufAdd + ks * 32);
                b[nt * 2 + 0][0] = r0; b[nt * 2 + 0][1] = r1;
                b[nt * 2 + 1][0] = r2; b[nt * 2 + 1][1] = r3;
            }
            #pragma unroll
            for (int mi = 0; mi < 2; mi++)
                #pragma unroll
                for (int ni = 0; ni < 8; ni++)
                    mma_f16(acc[mi][ni], a[mi][0], a[mi][1], a[mi][2], a[mi][3],
                            b[ni][0], b[ni][1]);
        }
        __syncthreads();
    }

    // ------------------- epilogue: distance + two-way mining -------------------
    const float* rsq = (const float*)(sb + OFF_RSQ);
    const int*   rlb = (const int*)(sb + OFF_RLB);
    const float* csq = (const float*)(sb + OFF_CSQ);
    const int*   clb = (const int*)(sb + OFF_CLB);

    const float INF = __int_as_float(0x7f800000);

    float apv[2][2], anv[2][2];
    float sqr[2][2]; int lbr[2][2];
    #pragma unroll
    for (int mi = 0; mi < 2; mi++)
        #pragma unroll
        for (int h = 0; h < 2; h++) {
            apv[mi][h] = 0.f;
            anv[mi][h] = INF;
            int r = wm * 32 + mi * 16 + h * 8 + (lane >> 2);
            sqr[mi][h] = rsq[r];
            lbr[mi][h] = rlb[r];
        }

    #pragma unroll
    for (int ni = 0; ni < 8; ni++) {
        const int jl = wn * 64 + ni * 8 + (lane & 3) * 2;
        float cap[2] = {0.f, 0.f};
        float can[2] = {INF, INF};
        #pragma unroll
        for (int e = 0; e < 2; e++) {
            const float sqj = csq[jl + e];
            const int   lj  = clb[jl + e];
            #pragma unroll
            for (int mi = 0; mi < 2; mi++)
                #pragma unroll
                for (int h = 0; h < 2; h++) {
                    float g = acc[mi][ni][h * 2 + e];
                    float d2 = fmaf(-2.f, g, sqr[mi][h] + sqj);
                    float dist = d2 > 0.f ? sqrtf(d2) : 0.f;
                    if (lbr[mi][h] == lj) {
                        apv[mi][h] = fmaxf(apv[mi][h], dist);
                        cap[e] = fmaxf(cap[e], dist);
                    } else {
                        anv[mi][h] = fminf(anv[mi][h], dist);
                        can[e] = fminf(can[e], dist);
                    }
                }
        }
        if (offdiag) {
            // column mining: reduce over lane>>2 groups (same lane&3 = same col)
            #pragma unroll
            for (int e = 0; e < 2; e++) {
                #pragma unroll
                for (int o = 4; o <= 16; o <<= 1) {
                    cap[e] = fmaxf(cap[e], __shfl_xor_sync(0xffffffffu, cap[e], o));
                    can[e] = fminf(can[e], __shfl_xor_sync(0xffffffffu, can[e], o));
                }
                if (lane < 4) {
                    int col = colBase + wn * 64 + ni * 8 + lane * 2 + e;
                    atomicMax((int*)&g_ap[col], __float_as_int(cap[e]));
                    atomicMin((int*)&g_an[col], __float_as_int(can[e]));
                }
            }
        }
    }

    // row-side reduction over 4 lanes sharing each row
    #pragma unroll
    for (int mi = 0; mi < 2; mi++)
        #pragma unroll
        for (int h = 0; h < 2; h++) {
            #pragma unroll
            for (int o = 1; o <= 2; o <<= 1) {
                apv[mi][h] = fmaxf(apv[mi][h], __shfl_xor_sync(0xffffffffu, apv[mi][h], o));
                anv[mi][h] = fminf(anv[mi][h], __shfl_xor_sync(0xffffffffu, anv[mi][h], o));
            }
        }
    if ((lane & 3) == 0) {
        #pragma unroll
        for (int mi = 0; mi < 2; mi++)
            #pragma unroll
            for (int h = 0; h < 2; h++) {
                int row = rowBase + wm * 32 + mi * 16 + h * 8 + (lane >> 2);
                atomicMax((int*)&g_ap[row], __float_as_int(apv[mi][h]));
                atomicMin((int*)&g_an[row], __float_as_int(anv[mi][h]));
            }
    }
}

// ---------------------------------------------------------------------------
// Kernel 3: final scalar loss
// ---------------------------------------------------------------------------
__global__ void loss_kernel(float* __restrict__ out) {
    __shared__ float ssum[256];
    __shared__ int   scnt[256];
    float s = 0.f; int c = 0;
    for (int i = threadIdx.x; i < N; i += 256) {
        float ap = g_ap[i];
        float an = g_an[i];
        if (ap > 0.f && isfinite(an)) {
            c++;
            float v = ap - an + MARGIN;
            s += v > 0.f ? v : 0.f;
        }
    }
    ssum[threadIdx.x] = s;
    scnt[threadIdx.x] = c;
    __syncthreads();
    for (int o = 128; o; o >>= 1) {
        if (threadIdx.x < o) {
            ssum[threadIdx.x] += ssum[threadIdx.x + o];
            scnt[threadIdx.x] += scnt[threadIdx.x + o];
        }
        __syncthreads();
    }
    if (threadIdx.x == 0) {
        int n = scnt[0];
        out[0] = (n > 0) ? (ssum[0] / (float)n) : 0.f;
    }
}

// ---------------------------------------------------------------------------
extern "C" void kernel_launch(void* const* d_in, const int* in_sizes, int n_in,
                              void* d_out, int out_size) {
    const float* F   = (const float*)d_in[0];
    const int*   lab = (const int*)d_in[1];
    float* out = (float*)d_out;

    cudaFuncSetAttribute(mma_mine_kernel,
                         cudaFuncAttributeMaxDynamicSharedMemorySize, SMEM_BYTES);

    prep_kernel<<<N, 256>>>(F, lab);
    mma_mine_kernel<<<NBLK, 256, SMEM_BYTES>>>();
    loss_kernel<<<1, 256>>>(out);
}